// round 7
// baseline (speedup 1.0000x reference)
#include <cuda_runtime.h>
#include <cstdint>

#define D 96
#define MAX_N 50000
#define MAXDEG 64
#define MAX_OVF 4096

// ---- scratch (static device globals; no allocation) -----------------------
__device__ float    g_aggr[MAX_N * D];          // tf32-rounded aggr + x
__device__ uint32_t g_wt[D * D];                // tf32-rounded W bits
__device__ int      g_cnt[MAX_N];               // per-node cursor / degree
__device__ int2     g_pack[MAX_N * MAXDEG];     // (src, bitcast(w)) buckets
__device__ int      g_ovfcnt;
__device__ int4     g_ovf[MAX_OVF];             // (src, dst, bitcast(w), pad)

__device__ __forceinline__ float to_tf32(float x) {
    float r;
    asm("cvt.rna.tf32.f32 %0, %1;" : "=f"(r) : "f"(x));
    return r;
}
__device__ __forceinline__ uint32_t smem_u32(const void* p) {
    uint32_t a;
    asm("{ .reg .u64 t; cvta.to.shared.u64 t, %1; cvt.u32.u64 %0, t; }"
        : "=r"(a) : "l"(p));
    return a;
}

// ---------------------------------------------------------------------------
// K1: zero cursors + overflow counter, AND pre-convert W to tf32 bits.
// ---------------------------------------------------------------------------
__global__ void zero_wconv_kernel(const float* __restrict__ Wm, int N) {
    int i = blockIdx.x * blockDim.x + threadIdx.x;
    if (i < N) g_cnt[i] = 0;
    if (i == 0) g_ovfcnt = 0;
    if (i < D * D) {
        uint32_t u;
        asm("cvt.rna.tf32.f32 %0, %1;" : "=r"(u) : "f"(__ldg(Wm + i)));
        g_wt[i] = u;
    }
}

// ---------------------------------------------------------------------------
// K2: bucket edges. 8 edges per thread, batched loads for MLP + deep
// in-flight atomic chains (kernel is atomic-latency bound, issue ~5%).
// ---------------------------------------------------------------------------
#define EPT 8
__global__ void bucket_kernel(const int* __restrict__ ei,
                              const float* __restrict__ ew,
                              const float* __restrict__ pr,
                              int E) {
    int base = (blockIdx.x * blockDim.x + threadIdx.x) * EPT;
    int src[EPT], dst[EPT];
    float w[EPT];
#pragma unroll
    for (int u = 0; u < EPT; u++) {
        int e = base + u;
        if (e < E) { src[u] = __ldg(ei + e); dst[u] = __ldg(ei + E + e); w[u] = __ldg(ew + e); }
    }
#pragma unroll
    for (int u = 0; u < EPT; u++) {
        int e = base + u;
        if (e < E) w[u] *= __ldg(pr + src[u]);
    }
#pragma unroll
    for (int u = 0; u < EPT; u++) {
        int e = base + u;
        if (e < E) {
            int pos = atomicAdd(&g_cnt[dst[u]], 1);
            if (pos < MAXDEG) {
                g_pack[dst[u] * MAXDEG + pos] = make_int2(src[u], __float_as_int(w[u]));
            } else {
                int o = atomicAdd(&g_ovfcnt, 1);
                if (o < MAX_OVF)
                    g_ovf[o] = make_int4(src[u], dst[u], __float_as_int(w[u]), 0);
            }
        }
    }
}

// ---------------------------------------------------------------------------
// K3: per-node aggregation. One warp per node; residual +x folded in.
// Gather loop unrolled x4 -> 12 independent coalesced loads in flight.
// Result written tf32-ROUNDED so the GEMM fill can be a raw async copy.
// ---------------------------------------------------------------------------
__global__ void aggregate_kernel(const float* __restrict__ x, int N) {
    __shared__ int2 s_pack[8][MAXDEG];

    int wid  = threadIdx.x >> 5;
    int l    = threadIdx.x & 31;
    int node = blockIdx.x * 8 + wid;
    if (node >= N) return;

    int cnt = g_cnt[node];
    if (cnt > MAXDEG) cnt = MAXDEG;

    const int2* bucket = g_pack + (size_t)node * MAXDEG;
    for (int k = l; k < cnt; k += 32)
        s_pack[wid][k] = __ldg(bucket + k);
    __syncwarp();

    const float* xr0 = x + (size_t)node * D;
    float a0 = __ldg(xr0 + l);
    float a1 = __ldg(xr0 + 32 + l);
    float a2 = __ldg(xr0 + 64 + l);

    int j = 0;
    for (; j + 4 <= cnt; j += 4) {
        int   s[4]; float w[4];
#pragma unroll
        for (int u = 0; u < 4; u++) {
            int2 p = s_pack[wid][j + u];
            s[u] = p.x; w[u] = __int_as_float(p.y);
        }
        float b0[4], b1[4], b2[4];
#pragma unroll
        for (int u = 0; u < 4; u++) {
            const float* xr = x + (size_t)s[u] * D;
            b0[u] = __ldg(xr + l);
            b1[u] = __ldg(xr + 32 + l);
            b2[u] = __ldg(xr + 64 + l);
        }
#pragma unroll
        for (int u = 0; u < 4; u++) {
            a0 += w[u] * b0[u];
            a1 += w[u] * b1[u];
            a2 += w[u] * b2[u];
        }
    }
    for (; j < cnt; j++) {
        int2 p = s_pack[wid][j];
        float w = __int_as_float(p.y);
        const float* xr = x + (size_t)p.x * D;
        a0 += w * __ldg(xr + l);
        a1 += w * __ldg(xr + 32 + l);
        a2 += w * __ldg(xr + 64 + l);
    }

    int ovf = g_ovfcnt;
    if (ovf > 0) {
        if (ovf > MAX_OVF) ovf = MAX_OVF;
        for (int i = 0; i < ovf; i++) {
            int4 p = g_ovf[i];
            if (p.y == node) {
                float w = __int_as_float(p.z);
                const float* xr = x + (size_t)p.x * D;
                a0 += w * __ldg(xr + l);
                a1 += w * __ldg(xr + 32 + l);
                a2 += w * __ldg(xr + 64 + l);
            }
        }
    }

    float* o = g_aggr + (size_t)node * D;
    o[l]      = to_tf32(a0);
    o[32 + l] = to_tf32(a1);
    o[64 + l] = to_tf32(a2);
}

// ---------------------------------------------------------------------------
// K4: tf32 mma.sync GEMM.  out[128 nodes x 96 cols] per CTA.
// 8 warps = 4 M-groups (32 rows) x 2 N-groups (48 cols).
// Warp tile: 2 m16 x 6 n8 subtiles, K=8/mma, 12 K-steps.
// Fills are pure cp.async.cg 16B copies (g_aggr / g_wt are pre-rounded tf32);
// out-of-range rows zero-filled via the src-size=0 form.
// smem pad 100 floats/row keeps all fragment LDS conflict-free.
// ---------------------------------------------------------------------------
#define LDP 100
#define NTILE 128
__global__ __launch_bounds__(256, 2)
void mma_gemm_kernel(const float* __restrict__ bias,
                     float* __restrict__ out,
                     int N) {
    extern __shared__ uint32_t smem[];
    uint32_t* sA = smem;                 // [128][LDP]
    uint32_t* sW = smem + NTILE * LDP;   // [96][LDP]
    uint32_t sA_b = smem_u32(sA);
    uint32_t sW_b = smem_u32(sW);

    int t   = threadIdx.x;               // 0..255
    int lid = t & 31;
    int wid = t >> 5;                    // 0..7
    int m0  = (wid & 3) * 32;
    int n0  = (wid >> 2) * 48;

    int row0 = blockIdx.x * NTILE;

    // async fill A tile: 128 rows x 24 float4
    const uint32_t* aggr_u = reinterpret_cast<const uint32_t*>(g_aggr);
    for (int i = t; i < NTILE * (D / 4); i += 256) {
        int r = i / (D / 4), c4 = i % (D / 4);
        int gr = row0 + r;
        const uint32_t* src = aggr_u + (size_t)gr * D + c4 * 4;
        uint32_t dst = sA_b + (uint32_t)(r * LDP + c4 * 4) * 4u;
        int sz = (gr < N) ? 16 : 0;
        asm volatile("cp.async.cg.shared.global [%0], [%1], 16, %2;"
                     :: "r"(dst), "l"(src), "r"(sz));
    }
    // async fill W tile: 96 rows x 24 float4
    for (int i = t; i < D * (D / 4); i += 256) {
        int r = i / (D / 4), c4 = i % (D / 4);
        const uint32_t* src = g_wt + (size_t)r * D + c4 * 4;
        uint32_t dst = sW_b + (uint32_t)(r * LDP + c4 * 4) * 4u;
        asm volatile("cp.async.cg.shared.global [%0], [%1], 16;"
                     :: "r"(dst), "l"(src));
    }
    asm volatile("cp.async.commit_group;");
    asm volatile("cp.async.wait_group 0;");
    __syncthreads();

    float c[2][6][4];
#pragma unroll
    for (int mt = 0; mt < 2; mt++)
#pragma unroll
        for (int nt = 0; nt < 6; nt++)
#pragma unroll
            for (int q = 0; q < 4; q++) c[mt][nt][q] = 0.f;

    int arow = lid >> 2;                 // 0..7
    int acol = lid & 3;                  // 0..3

#pragma unroll
    for (int ks = 0; ks < 12; ks++) {
        int k0 = ks * 8;

        uint32_t a[2][4];
#pragma unroll
        for (int mt = 0; mt < 2; mt++) {
            const uint32_t* base = sA + (m0 + mt * 16 + arow) * LDP + k0 + acol;
            a[mt][0] = base[0];
            a[mt][1] = base[8 * LDP];
            a[mt][2] = base[4];
            a[mt][3] = base[8 * LDP + 4];
        }
        uint32_t bfr[6][2];
#pragma unroll
        for (int nt = 0; nt < 6; nt++) {
            const uint32_t* base = sW + (n0 + nt * 8 + arow) * LDP + k0 + acol;
            bfr[nt][0] = base[0];
            bfr[nt][1] = base[4];
        }

#pragma unroll
        for (int mt = 0; mt < 2; mt++)
#pragma unroll
            for (int nt = 0; nt < 6; nt++) {
                asm volatile(
                    "mma.sync.aligned.m16n8k8.row.col.f32.tf32.tf32.f32 "
                    "{%0,%1,%2,%3}, {%4,%5,%6,%7}, {%8,%9}, {%0,%1,%2,%3};"
                    : "+f"(c[mt][nt][0]), "+f"(c[mt][nt][1]),
                      "+f"(c[mt][nt][2]), "+f"(c[mt][nt][3])
                    : "r"(a[mt][0]), "r"(a[mt][1]), "r"(a[mt][2]), "r"(a[mt][3]),
                      "r"(bfr[nt][0]), "r"(bfr[nt][1]));
            }
    }

    // epilogue: c0,c1 -> (row, 2c),(row, 2c+1); c2,c3 -> row+8
#pragma unroll
    for (int nt = 0; nt < 6; nt++) {
        int col = n0 + nt * 8 + 2 * acol;
        float b0 = __ldg(bias + col);
        float b1 = __ldg(bias + col + 1);
#pragma unroll
        for (int mt = 0; mt < 2; mt++) {
            int r_lo = row0 + m0 + mt * 16 + arow;
            if (r_lo < N) {
                float2 v = make_float2(c[mt][nt][0] + b0, c[mt][nt][1] + b1);
                *reinterpret_cast<float2*>(out + (size_t)r_lo * D + col) = v;
            }
            int r_hi = r_lo + 8;
            if (r_hi < N) {
                float2 v = make_float2(c[mt][nt][2] + b0, c[mt][nt][3] + b1);
                *reinterpret_cast<float2*>(out + (size_t)r_hi * D + col) = v;
            }
        }
    }
}

// ---------------------------------------------------------------------------
// Launch. Inputs: x[N*D] f32, edge_index[2*E] i32, edge_weight[E] f32,
//                 pagerank[N] f32, W[D*D] f32, b[D] f32. Output f32 [N,D].
// ---------------------------------------------------------------------------
extern "C" void kernel_launch(void* const* d_in, const int* in_sizes, int n_in,
                              void* d_out, int out_size) {
    const float* x  = (const float*)d_in[0];
    const int*   ei = (const int*)  d_in[1];
    const float* ew = (const float*)d_in[2];
    const float* pr = (const float*)d_in[3];
    const float* Wm = (const float*)d_in[4];
    const float* b  = (const float*)d_in[5];
    float* out = (float*)d_out;

    int N = in_sizes[0] / D;
    int E = in_sizes[1] / 2;

    const int gemm_smem = (NTILE * LDP + D * LDP) * (int)sizeof(uint32_t);
    cudaFuncSetAttribute(mma_gemm_kernel,
                         cudaFuncAttributeMaxDynamicSharedMemorySize, gemm_smem);

    zero_wconv_kernel<<<(N + 255) / 256, 256>>>(Wm, N);

    int nthread = (E + EPT - 1) / EPT;
    bucket_kernel<<<(nthread + 255) / 256, 256>>>(ei, ew, pr, E);

    aggregate_kernel<<<(N + 7) / 8, 256>>>(x, N);

    mma_gemm_kernel<<<(N + NTILE - 1) / NTILE, 256, gemm_smem>>>(b, out, N);
}

// round 8
// speedup vs baseline: 1.1765x; 1.1765x over previous
#include <cuda_runtime.h>
#include <cstdint>

#define D 96
#define MAX_N 50000
#define MAXDEG 64
#define MAX_OVF 4096

// ---- scratch (static device globals; no allocation) -----------------------
__device__ float    g_aggr[MAX_N * D];          // tf32-rounded aggr + x
__device__ uint32_t g_wt[D * D];                // tf32-rounded W bits
__device__ int      g_cnt[MAX_N];               // per-node cursor / degree
__device__ int2     g_pack[MAX_N * MAXDEG];     // (src, bitcast(w)) buckets
__device__ int      g_ovfcnt;
__device__ int4     g_ovf[MAX_OVF];             // (src, dst, bitcast(w), pad)

__device__ __forceinline__ float to_tf32(float x) {
    float r;
    asm("cvt.rna.tf32.f32 %0, %1;" : "=f"(r) : "f"(x));
    return r;
}
__device__ __forceinline__ uint32_t smem_u32(const void* p) {
    uint32_t a;
    asm("{ .reg .u64 t; cvta.to.shared.u64 t, %1; cvt.u32.u64 %0, t; }"
        : "=r"(a) : "l"(p));
    return a;
}

// ---------------------------------------------------------------------------
// K1: zero cursors + overflow counter, AND pre-convert W to tf32 bits.
// ---------------------------------------------------------------------------
__global__ void zero_wconv_kernel(const float* __restrict__ Wm, int N) {
    int i = blockIdx.x * blockDim.x + threadIdx.x;
    if (i < N) g_cnt[i] = 0;
    if (i == 0) g_ovfcnt = 0;
    if (i < D * D) {
        uint32_t u;
        asm("cvt.rna.tf32.f32 %0, %1;" : "=r"(u) : "f"(__ldg(Wm + i)));
        g_wt[i] = u;
    }
}

// ---------------------------------------------------------------------------
// K2: bucket edges. 4 edges per thread (EPT=8 regressed: kernel is
// atomic-LATENCY bound and needs thread-level parallelism, not depth).
// ---------------------------------------------------------------------------
#define EPT 4
__global__ void bucket_kernel(const int* __restrict__ ei,
                              const float* __restrict__ ew,
                              const float* __restrict__ pr,
                              int E) {
    int base = (blockIdx.x * blockDim.x + threadIdx.x) * EPT;
    int src[EPT], dst[EPT];
    float w[EPT];
#pragma unroll
    for (int u = 0; u < EPT; u++) {
        int e = base + u;
        if (e < E) { src[u] = __ldg(ei + e); dst[u] = __ldg(ei + E + e); w[u] = __ldg(ew + e); }
    }
#pragma unroll
    for (int u = 0; u < EPT; u++) {
        int e = base + u;
        if (e < E) w[u] *= __ldg(pr + src[u]);
    }
#pragma unroll
    for (int u = 0; u < EPT; u++) {
        int e = base + u;
        if (e < E) {
            int pos = atomicAdd(&g_cnt[dst[u]], 1);
            if (pos < MAXDEG) {
                g_pack[dst[u] * MAXDEG + pos] = make_int2(src[u], __float_as_int(w[u]));
            } else {
                int o = atomicAdd(&g_ovfcnt, 1);
                if (o < MAX_OVF)
                    g_ovf[o] = make_int4(src[u], dst[u], __float_as_int(w[u]), 0);
            }
        }
    }
}

// ---------------------------------------------------------------------------
// K3: per-node aggregation. One warp per node; residual +x folded in.
// Gather loop unrolled x4 -> 12 independent coalesced loads in flight.
// Result written tf32-ROUNDED so the GEMM fill can be a raw async copy.
// ---------------------------------------------------------------------------
__global__ void aggregate_kernel(const float* __restrict__ x, int N) {
    __shared__ int2 s_pack[8][MAXDEG];

    int wid  = threadIdx.x >> 5;
    int l    = threadIdx.x & 31;
    int node = blockIdx.x * 8 + wid;
    if (node >= N) return;

    int cnt = g_cnt[node];
    if (cnt > MAXDEG) cnt = MAXDEG;

    const int2* bucket = g_pack + (size_t)node * MAXDEG;
    for (int k = l; k < cnt; k += 32)
        s_pack[wid][k] = __ldg(bucket + k);
    __syncwarp();

    const float* xr0 = x + (size_t)node * D;
    float a0 = __ldg(xr0 + l);
    float a1 = __ldg(xr0 + 32 + l);
    float a2 = __ldg(xr0 + 64 + l);

    int j = 0;
    for (; j + 4 <= cnt; j += 4) {
        int   s[4]; float w[4];
#pragma unroll
        for (int u = 0; u < 4; u++) {
            int2 p = s_pack[wid][j + u];
            s[u] = p.x; w[u] = __int_as_float(p.y);
        }
        float b0[4], b1[4], b2[4];
#pragma unroll
        for (int u = 0; u < 4; u++) {
            const float* xr = x + (size_t)s[u] * D;
            b0[u] = __ldg(xr + l);
            b1[u] = __ldg(xr + 32 + l);
            b2[u] = __ldg(xr + 64 + l);
        }
#pragma unroll
        for (int u = 0; u < 4; u++) {
            a0 += w[u] * b0[u];
            a1 += w[u] * b1[u];
            a2 += w[u] * b2[u];
        }
    }
    for (; j < cnt; j++) {
        int2 p = s_pack[wid][j];
        float w = __int_as_float(p.y);
        const float* xr = x + (size_t)p.x * D;
        a0 += w * __ldg(xr + l);
        a1 += w * __ldg(xr + 32 + l);
        a2 += w * __ldg(xr + 64 + l);
    }

    int ovf = g_ovfcnt;
    if (ovf > 0) {
        if (ovf > MAX_OVF) ovf = MAX_OVF;
        for (int i = 0; i < ovf; i++) {
            int4 p = g_ovf[i];
            if (p.y == node) {
                float w = __int_as_float(p.z);
                const float* xr = x + (size_t)p.x * D;
                a0 += w * __ldg(xr + l);
                a1 += w * __ldg(xr + 32 + l);
                a2 += w * __ldg(xr + 64 + l);
            }
        }
    }

    float* o = g_aggr + (size_t)node * D;
    o[l]      = to_tf32(a0);
    o[32 + l] = to_tf32(a1);
    o[64 + l] = to_tf32(a2);
}

// ---------------------------------------------------------------------------
// K4: tf32 mma.sync GEMM.  out[128 nodes x 96 cols] per CTA.
// 8 warps = 4 M-groups (32 rows) x 2 N-groups (48 cols).
// Warp tile: 2 m16 x 6 n8 subtiles, K=8/mma, 12 K-steps.
// Fills are pure cp.async.cg 16B copies (g_aggr / g_wt are pre-rounded tf32);
// out-of-range rows zero-filled via the src-size=0 form.
// smem pad 100 floats/row keeps all fragment LDS conflict-free.
// ---------------------------------------------------------------------------
#define LDP 100
#define NTILE 128
__global__ __launch_bounds__(256, 2)
void mma_gemm_kernel(const float* __restrict__ bias,
                     float* __restrict__ out,
                     int N) {
    extern __shared__ uint32_t smem[];
    uint32_t* sA = smem;                 // [128][LDP]
    uint32_t* sW = smem + NTILE * LDP;   // [96][LDP]
    uint32_t sA_b = smem_u32(sA);
    uint32_t sW_b = smem_u32(sW);

    int t   = threadIdx.x;               // 0..255
    int lid = t & 31;
    int wid = t >> 5;                    // 0..7
    int m0  = (wid & 3) * 32;
    int n0  = (wid >> 2) * 48;

    int row0 = blockIdx.x * NTILE;

    // async fill A tile: 128 rows x 24 float4
    const uint32_t* aggr_u = reinterpret_cast<const uint32_t*>(g_aggr);
    for (int i = t; i < NTILE * (D / 4); i += 256) {
        int r = i / (D / 4), c4 = i % (D / 4);
        int gr = row0 + r;
        const uint32_t* src = aggr_u + (size_t)gr * D + c4 * 4;
        uint32_t dst = sA_b + (uint32_t)(r * LDP + c4 * 4) * 4u;
        int sz = (gr < N) ? 16 : 0;
        asm volatile("cp.async.cg.shared.global [%0], [%1], 16, %2;"
                     :: "r"(dst), "l"(src), "r"(sz));
    }
    // async fill W tile: 96 rows x 24 float4
    for (int i = t; i < D * (D / 4); i += 256) {
        int r = i / (D / 4), c4 = i % (D / 4);
        const uint32_t* src = g_wt + (size_t)r * D + c4 * 4;
        uint32_t dst = sW_b + (uint32_t)(r * LDP + c4 * 4) * 4u;
        asm volatile("cp.async.cg.shared.global [%0], [%1], 16;"
                     :: "r"(dst), "l"(src));
    }
    asm volatile("cp.async.commit_group;");
    asm volatile("cp.async.wait_group 0;");
    __syncthreads();

    float c[2][6][4];
#pragma unroll
    for (int mt = 0; mt < 2; mt++)
#pragma unroll
        for (int nt = 0; nt < 6; nt++)
#pragma unroll
            for (int q = 0; q < 4; q++) c[mt][nt][q] = 0.f;

    int arow = lid >> 2;                 // 0..7
    int acol = lid & 3;                  // 0..3

#pragma unroll
    for (int ks = 0; ks < 12; ks++) {
        int k0 = ks * 8;

        uint32_t a[2][4];
#pragma unroll
        for (int mt = 0; mt < 2; mt++) {
            const uint32_t* base = sA + (m0 + mt * 16 + arow) * LDP + k0 + acol;
            a[mt][0] = base[0];
            a[mt][1] = base[8 * LDP];
            a[mt][2] = base[4];
            a[mt][3] = base[8 * LDP + 4];
        }
        uint32_t bfr[6][2];
#pragma unroll
        for (int nt = 0; nt < 6; nt++) {
            const uint32_t* base = sW + (n0 + nt * 8 + arow) * LDP + k0 + acol;
            bfr[nt][0] = base[0];
            bfr[nt][1] = base[4];
        }

#pragma unroll
        for (int mt = 0; mt < 2; mt++)
#pragma unroll
            for (int nt = 0; nt < 6; nt++) {
                asm volatile(
                    "mma.sync.aligned.m16n8k8.row.col.f32.tf32.tf32.f32 "
                    "{%0,%1,%2,%3}, {%4,%5,%6,%7}, {%8,%9}, {%0,%1,%2,%3};"
                    : "+f"(c[mt][nt][0]), "+f"(c[mt][nt][1]),
                      "+f"(c[mt][nt][2]), "+f"(c[mt][nt][3])
                    : "r"(a[mt][0]), "r"(a[mt][1]), "r"(a[mt][2]), "r"(a[mt][3]),
                      "r"(bfr[nt][0]), "r"(bfr[nt][1]));
            }
    }

    // epilogue: c0,c1 -> (row, 2c),(row, 2c+1); c2,c3 -> row+8
#pragma unroll
    for (int nt = 0; nt < 6; nt++) {
        int col = n0 + nt * 8 + 2 * acol;
        float b0 = __ldg(bias + col);
        float b1 = __ldg(bias + col + 1);
#pragma unroll
        for (int mt = 0; mt < 2; mt++) {
            int r_lo = row0 + m0 + mt * 16 + arow;
            if (r_lo < N) {
                float2 v = make_float2(c[mt][nt][0] + b0, c[mt][nt][1] + b1);
                *reinterpret_cast<float2*>(out + (size_t)r_lo * D + col) = v;
            }
            int r_hi = r_lo + 8;
            if (r_hi < N) {
                float2 v = make_float2(c[mt][nt][2] + b0, c[mt][nt][3] + b1);
                *reinterpret_cast<float2*>(out + (size_t)r_hi * D + col) = v;
            }
        }
    }
}

// ---------------------------------------------------------------------------
// Launch. Inputs: x[N*D] f32, edge_index[2*E] i32, edge_weight[E] f32,
//                 pagerank[N] f32, W[D*D] f32, b[D] f32. Output f32 [N,D].
// ---------------------------------------------------------------------------
extern "C" void kernel_launch(void* const* d_in, const int* in_sizes, int n_in,
                              void* d_out, int out_size) {
    const float* x  = (const float*)d_in[0];
    const int*   ei = (const int*)  d_in[1];
    const float* ew = (const float*)d_in[2];
    const float* pr = (const float*)d_in[3];
    const float* Wm = (const float*)d_in[4];
    const float* b  = (const float*)d_in[5];
    float* out = (float*)d_out;

    int N = in_sizes[0] / D;
    int E = in_sizes[1] / 2;

    const int gemm_smem = (NTILE * LDP + D * LDP) * (int)sizeof(uint32_t);
    cudaFuncSetAttribute(mma_gemm_kernel,
                         cudaFuncAttributeMaxDynamicSharedMemorySize, gemm_smem);

    zero_wconv_kernel<<<(N + 255) / 256, 256>>>(Wm, N);

    int nthread = (E + EPT - 1) / EPT;
    bucket_kernel<<<(nthread + 255) / 256, 256>>>(ei, ew, pr, E);

    aggregate_kernel<<<(N + 7) / 8, 256>>>(x, N);

    mma_gemm_kernel<<<(N + NTILE - 1) / NTILE, 256, gemm_smem>>>(b, out, N);
}